// round 1
// baseline (speedup 1.0000x reference)
#include <cuda_runtime.h>
#include <math.h>

#define BB 256
#define TT 100
#define NINN 64
#define HH 1024
#define KT 32

// Persistent state: double-buffered h (t parity) per layer, c per layer.
// h must be double-buffered: every block reads the full h_{t-1} of its layer
// during the GEMM while blocks write h_t -> separate buffers avoid the race.
// c[b][j] is read+written only by the thread owning (b,j) -> safe in place.
__device__ float g_h[2][4][BB * HH];
__device__ float g_c[4][BB * HH];

__global__ void zero_state() {
    int i = blockIdx.x * blockDim.x + threadIdx.x;
    if (i < BB * HH) {
        #pragma unroll
        for (int l = 0; l < 4; l++) {
            g_h[0][l][i] = 0.f;
            g_h[1][l][i] = 0.f;
            g_c[l][i]    = 0.f;
        }
    }
}

// One LSTM cell step: gates[B,4H] = A0 @ Wih^T + h_prev @ Whh^T + bih + bhh,
// then activations, c update, h write (+ optional sequence output for layer 3).
// Block tile: 64 rows (batch) x 32 cols x 4 gates. 256 threads.
// Thread: col = tid&31, owns 8 consecutive rows, all 4 gates at its column ->
// epilogue is purely thread-local.
__global__ __launch_bounds__(256) void lstm_cell(
    const float* __restrict__ x, int ldx, int din,
    int layer, int buf,
    const float* __restrict__ Wih, const float* __restrict__ Whh,
    const float* __restrict__ bih, const float* __restrict__ bhh,
    float* __restrict__ outp /* d_out + t*H for layer 3, else nullptr */)
{
    __shared__ float As[64][KT + 1];    // +1 pad: broadcast reads, clean stores
    __shared__ float Ws[128][KT + 1];   // stride 33 -> conflict-free lane reads

    const int tid  = threadIdx.x;
    const int col  = tid & 31;          // 0..31 (lane)
    const int rowg = tid >> 5;          // 0..7  (warp id)
    const int r0   = rowg * 8;
    const int bn   = blockIdx.x;        // 0..31 column tile (within H)
    const int bm   = blockIdx.y;        // 0..3  row tile (within B)
    const int cg   = bn * 32 + col;     // global column in [0,H)

    const float* hin  = g_h[buf ^ 1][layer];
    float*       hout = g_h[buf][layer];
    float*       cst  = g_c[layer];
    const float* A0   = (layer == 0) ? x : g_h[buf][layer - 1];
    const int    lda0 = (layer == 0) ? ldx : HH;

    float acc[4][8];
    #pragma unroll
    for (int g = 0; g < 4; g++)
        #pragma unroll
        for (int i = 0; i < 8; i++) acc[g][i] = 0.f;

    #pragma unroll 1
    for (int phase = 0; phase < 2; phase++) {
        const float* Ap  = phase ? hin : A0;
        const int    ldA = phase ? HH : lda0;
        const float* Wp  = phase ? Whh : Wih;
        const int    ldW = phase ? HH : din;
        const int    K   = phase ? HH : din;

        for (int k0 = 0; k0 < K; k0 += KT) {
            // A tile: 64 x KT. Warp covers one row per iter, k = lane -> coalesced.
            #pragma unroll
            for (int i = tid; i < 64 * KT; i += 256) {
                int r = i >> 5;
                int k = i & (KT - 1);
                As[r][k] = Ap[(bm * 64 + r) * ldA + k0 + k];
            }
            // W tile: 128 gate-rows x KT. Row j = gate*H + bn*32 + local.
            #pragma unroll
            for (int i = tid; i < 128 * KT; i += 256) {
                int wr   = i >> 5;
                int k    = i & (KT - 1);
                int gate = wr >> 5;
                int cl   = wr & 31;
                Ws[wr][k] = Wp[(gate * HH + bn * 32 + cl) * ldW + k0 + k];
            }
            __syncthreads();

            #pragma unroll
            for (int k = 0; k < KT; k++) {
                float a[8];
                #pragma unroll
                for (int i = 0; i < 8; i++) a[i] = As[r0 + i][k];  // warp-broadcast
                #pragma unroll
                for (int g = 0; g < 4; g++) {
                    float w = Ws[g * 32 + col][k];                  // conflict-free
                    #pragma unroll
                    for (int i = 0; i < 8; i++)
                        acc[g][i] = fmaf(a[i], w, acc[g][i]);
                }
            }
            __syncthreads();
        }
    }

    const float bi = bih[cg]          + bhh[cg];
    const float bf = bih[HH + cg]     + bhh[HH + cg];
    const float bg = bih[2 * HH + cg] + bhh[2 * HH + cg];
    const float bo = bih[3 * HH + cg] + bhh[3 * HH + cg];

    #pragma unroll
    for (int i = 0; i < 8; i++) {
        int   b  = bm * 64 + r0 + i;
        float vi = acc[0][i] + bi;
        float vf = acc[1][i] + bf;
        float vg = acc[2][i] + bg;
        float vo = acc[3][i] + bo;
        float is = 1.f / (1.f + expf(-vi));
        float fs = 1.f / (1.f + expf(-vf));
        float gt = tanhf(vg);
        float os = 1.f / (1.f + expf(-vo));
        float cn = fs * cst[b * HH + cg] + is * gt;
        cst[b * HH + cg] = cn;
        float hn = os * tanhf(cn);
        hout[b * HH + cg] = hn;
        if (outp) outp[(size_t)b * (TT * HH) + cg] = hn;  // out[b][t][cg]
    }
}

__global__ void copy_c4(float* __restrict__ out) {
    int i = blockIdx.x * blockDim.x + threadIdx.x;
    if (i < BB * HH) out[i] = g_c[3][i];
}

extern "C" void kernel_launch(void* const* d_in, const int* in_sizes, int n_in,
                              void* d_out, int out_size) {
    const float* x = (const float*)d_in[0];
    const float* W[4][4];  // [layer][Wih, Whh, bih, bhh]
    for (int l = 0; l < 4; l++)
        for (int j = 0; j < 4; j++)
            W[l][j] = (const float*)d_in[1 + l * 4 + j];
    float* out = (float*)d_out;

    zero_state<<<(BB * HH + 255) / 256, 256>>>();

    dim3 grid(HH / 32, BB / 64);  // 32 x 4 = 128 blocks
    for (int t = 0; t < TT; t++) {
        int buf = t & 1;
        for (int l = 0; l < 4; l++) {
            const float* xin = (l == 0) ? (x + (size_t)t * NINN) : nullptr;
            int din = (l == 0) ? NINN : HH;
            float* outp = (l == 3) ? (out + (size_t)t * HH) : nullptr;
            lstm_cell<<<grid, 256>>>(xin, TT * NINN, din, l, buf,
                                     W[l][0], W[l][1], W[l][2], W[l][3], outp);
        }
    }

    copy_c4<<<(BB * HH + 255) / 256, 256>>>(out + (size_t)BB * TT * HH);
}

// round 5
// speedup vs baseline: 5.9218x; 5.9218x over previous
#include <cuda_runtime.h>
#include <cuda_fp16.h>
#include <math.h>
#include <stdint.h>

#define BB 256
#define TT 100
#define NINN 64
#define HH 1024

// ---------------- persistent device state ----------------
__device__ __half g_x16[BB * TT * NINN];          // fp16 copy of x
__device__ __half g_wih0[4 * HH * NINN];          // layer 0 Wih
__device__ __half g_wih[3][4 * HH * HH];          // layers 1-3 Wih
__device__ __half g_whh[4][4 * HH * HH];          // Whh
__device__ __half g_h16[2][4][BB * HH];           // h state, double buffered (t parity)
__device__ float  g_c[4][BB * HH];                // c state (fp32)
__device__ float  g_bias[4][4 * HH];              // bih + bhh per layer

// ---------------- conversion / init ----------------
__global__ void conv_all(const float* __restrict__ x,
    const float* __restrict__ wi1, const float* __restrict__ wh1,
    const float* __restrict__ wi2, const float* __restrict__ wh2,
    const float* __restrict__ wi3, const float* __restrict__ wh3,
    const float* __restrict__ wi4, const float* __restrict__ wh4)
{
    const long NX  = BB * TT * NINN;      // 1,638,400
    const long NW0 = 4 * HH * NINN;       //   262,144
    const long NW  = 4L * HH * HH;        // 4,194,304
    const long total = NX + NW0 + 7L * NW;
    for (long i = blockIdx.x * (long)blockDim.x + threadIdx.x; i < total;
         i += (long)gridDim.x * blockDim.x) {
        long j = i;
        if (j < NX)  { g_x16[j]    = __float2half(x[j]);   continue; } j -= NX;
        if (j < NW0) { g_wih0[j]   = __float2half(wi1[j]); continue; } j -= NW0;
        if (j < NW)  { g_whh[0][j] = __float2half(wh1[j]); continue; } j -= NW;
        if (j < NW)  { g_wih[0][j] = __float2half(wi2[j]); continue; } j -= NW;
        if (j < NW)  { g_whh[1][j] = __float2half(wh2[j]); continue; } j -= NW;
        if (j < NW)  { g_wih[1][j] = __float2half(wi3[j]); continue; } j -= NW;
        if (j < NW)  { g_whh[2][j] = __float2half(wh3[j]); continue; } j -= NW;
        if (j < NW)  { g_wih[2][j] = __float2half(wi4[j]); continue; } j -= NW;
        g_whh[3][j] = __float2half(wh4[j]);
    }
}

__global__ void init_state(
    const float* __restrict__ bi1, const float* __restrict__ bh1,
    const float* __restrict__ bi2, const float* __restrict__ bh2,
    const float* __restrict__ bi3, const float* __restrict__ bh3,
    const float* __restrict__ bi4, const float* __restrict__ bh4)
{
    int i = blockIdx.x * blockDim.x + threadIdx.x;
    if (i < BB * HH) {
        __half z = __float2half(0.f);
        #pragma unroll
        for (int l = 0; l < 4; l++) {
            g_h16[0][l][i] = z;
            g_h16[1][l][i] = z;
            g_c[l][i] = 0.f;
        }
    }
    if (i < 4 * HH) {
        g_bias[0][i] = bi1[i] + bh1[i];
        g_bias[1][i] = bi2[i] + bh2[i];
        g_bias[2][i] = bi3[i] + bh3[i];
        g_bias[3][i] = bi4[i] + bh4[i];
    }
}

// ---------------- helpers ----------------
__device__ __forceinline__ uint32_t swz(uint32_t x) { return x ^ ((x >> 3) & 0x70); }

__device__ __forceinline__ void cpa16(uint32_t s, const void* g) {
    asm volatile("cp.async.cg.shared.global [%0], [%1], 16;" :: "r"(s), "l"(g));
}
__device__ __forceinline__ void ldm4(uint32_t* r, uint32_t a) {
    asm volatile("ldmatrix.sync.aligned.m8n8.x4.shared.b16 {%0,%1,%2,%3}, [%4];"
        : "=r"(r[0]), "=r"(r[1]), "=r"(r[2]), "=r"(r[3]) : "r"(a));
}
__device__ __forceinline__ void mma16816(float* d, const uint32_t* a, const uint32_t* b) {
    asm volatile(
        "mma.sync.aligned.m16n8k16.row.col.f32.f16.f16.f32 "
        "{%0,%1,%2,%3}, {%4,%5,%6,%7}, {%8,%9}, {%0,%1,%2,%3};"
        : "+f"(d[0]), "+f"(d[1]), "+f"(d[2]), "+f"(d[3])
        : "r"(a[0]), "r"(a[1]), "r"(a[2]), "r"(a[3]), "r"(b[0]), "r"(b[1]));
}

// smem: A bufs [2][64 rows][128B] @0, B bufs [2][128 rows][128B] @16384
// epilogue stage: float S[64][132] reuses the same storage after a sync.
#define A_OFF(b) ((b) * 8192)
#define B_OFF(b) (16384 + (b) * 16384)
#define SMEM_BYTES 49152

// Load one K-tile (A: 64x64 fp16, B: 128x64 fp16) into smem buffer b.
__device__ __forceinline__ void load_tile(
    uint32_t sb, int tid, int b, int m0, int nh0,
    const __half* __restrict__ Ap, int ldA,
    const __half* __restrict__ Wp, int ldW, int k0)
{
    // A: 64 rows x 128B -> 512 x 16B chunks (8 threads per row -> coalesced)
    #pragma unroll
    for (int i = 0; i < 2; i++) {
        int u = tid + i * 256;
        int r = u >> 3, c = u & 7;
        cpa16(sb + A_OFF(b) + swz(r * 128 + c * 16),
              Ap + (size_t)(m0 + r) * ldA + k0 + c * 8);
    }
    // B: 128 rows (gate*32+col) x 128B -> 1024 chunks
    #pragma unroll
    for (int i = 0; i < 4; i++) {
        int u = tid + i * 256;
        int rr = u >> 3, c = u & 7;
        int wrow = (rr >> 5) * HH + nh0 + (rr & 31);
        cpa16(sb + B_OFF(b) + swz(rr * 128 + c * 16),
              Wp + (size_t)wrow * ldW + k0 + c * 8);
    }
    asm volatile("cp.async.commit_group;" ::: "memory");
}

// One LSTM cell. CTA: 64 batch rows x (4 gates x 32 hidden cols), K pipelined.
__global__ __launch_bounds__(256, 1) void lstm_cell(
    int t, int layer, int buf, float* __restrict__ out)
{
    extern __shared__ __align__(16) unsigned char SM[];
    const uint32_t sb = (uint32_t)__cvta_generic_to_shared(SM);

    const int tid  = threadIdx.x;
    const int lane = tid & 31;
    const int w    = tid >> 5;
    const int mw   = w >> 2;          // 0..1 : 32-row m strip
    const int nw   = w & 3;           // 0..3 : 32-col n strip (gate-major layout)
    const int nh0  = blockIdx.x * 32; // hidden-col tile
    const int m0   = blockIdx.y * 64; // batch-row tile

    const int din = (layer == 0) ? NINN : HH;
    const __half* A0   = (layer == 0) ? (g_x16 + t * NINN) : g_h16[buf][layer - 1];
    const int     ldA0 = (layer == 0) ? TT * NINN : HH;
    const __half* Wih  = (layer == 0) ? g_wih0 : g_wih[layer - 1];
    const __half* Whh  = g_whh[layer];
    const __half* hin  = g_h16[buf ^ 1][layer];
    __half*       hout = g_h16[buf][layer];
    float*        cst  = g_c[layer];

    const int nt0 = din / 64;          // K tiles in input phase
    const int ntt = nt0 + HH / 64;     // + recurrent phase

    float acc[2][4][4];
    #pragma unroll
    for (int mt = 0; mt < 2; mt++)
        #pragma unroll
        for (int nt = 0; nt < 4; nt++)
            #pragma unroll
            for (int i = 0; i < 4; i++) acc[mt][nt][i] = 0.f;

    load_tile(sb, tid, 0, m0, nh0, A0, ldA0, Wih, din, 0);
    for (int j = 0; j < ntt; j++) {
        int b = j & 1;
        if (j + 1 < ntt) {
            int jn = j + 1;
            if (jn < nt0) load_tile(sb, tid, b ^ 1, m0, nh0, A0, ldA0, Wih, din, jn * 64);
            else          load_tile(sb, tid, b ^ 1, m0, nh0, hin, HH, Whh, HH, (jn - nt0) * 64);
            asm volatile("cp.async.wait_group 1;" ::: "memory");
        } else {
            asm volatile("cp.async.wait_group 0;" ::: "memory");
        }
        __syncthreads();

        const uint32_t sA = sb + A_OFF(b);
        const uint32_t sB = sb + B_OFF(b);
        #pragma unroll
        for (int ks = 0; ks < 4; ks++) {
            uint32_t a[2][4];
            #pragma unroll
            for (int mt = 0; mt < 2; mt++) {
                int r  = mw * 32 + mt * 16 + (lane & 15);
                int kc = ks * 32 + (lane >> 4) * 16;   // bytes within row
                ldm4(a[mt], sA + swz(r * 128 + kc));
            }
            uint32_t bf[4][2];
            #pragma unroll
            for (int np = 0; np < 2; np++) {
                int rr = nw * 32 + np * 16 + (lane & 7) + ((lane >> 4) << 3);
                int kc = ks * 32 + (((lane >> 3) & 1) << 4);
                uint32_t r4[4];
                ldm4(r4, sB + swz(rr * 128 + kc));
                bf[np * 2 + 0][0] = r4[0]; bf[np * 2 + 0][1] = r4[1];
                bf[np * 2 + 1][0] = r4[2]; bf[np * 2 + 1][1] = r4[3];
            }
            #pragma unroll
            for (int mt = 0; mt < 2; mt++)
                #pragma unroll
                for (int nt = 0; nt < 4; nt++)
                    mma16816(acc[mt][nt], a[mt], bf[nt]);
        }
        __syncthreads();
    }

    // ---- stage accums to smem so each thread owns all 4 gates of (b, col) ----
    float* S = (float*)SM;  // [64][132]
    #pragma unroll
    for (int mt = 0; mt < 2; mt++)
        #pragma unroll
        for (int nt = 0; nt < 4; nt++) {
            int r = mw * 32 + mt * 16 + (lane >> 2);
            int c = nw * 32 + nt * 8 + 2 * (lane & 3);
            *(float2*)&S[r * 132 + c]       = make_float2(acc[mt][nt][0], acc[mt][nt][1]);
            *(float2*)&S[(r + 8) * 132 + c] = make_float2(acc[mt][nt][2], acc[mt][nt][3]);
        }
    __syncthreads();

    const int hc = tid & 31;  // hidden col (constant per thread)
    const float* bias = g_bias[layer];
    float bi  = bias[0 * HH + nh0 + hc];
    float bf_ = bias[1 * HH + nh0 + hc];
    float bg  = bias[2 * HH + nh0 + hc];
    float bo  = bias[3 * HH + nh0 + hc];

    #pragma unroll
    for (int i = 0; i < 8; i++) {
        int bl  = (tid >> 5) + i * 8;      // local batch row
        int bg_ = m0 + bl;                 // global batch row
        float vi = S[bl * 132 +   0 + hc] + bi;
        float vf = S[bl * 132 +  32 + hc] + bf_;
        float vg = S[bl * 132 +  64 + hc] + bg;
        float vo = S[bl * 132 +  96 + hc] + bo;
        float is = 1.f / (1.f + expf(-vi));
        float fs = 1.f / (1.f + expf(-vf));
        float gt = tanhf(vg);
        float os = 1.f / (1.f + expf(-vo));
        size_t ci = (size_t)bg_ * HH + nh0 + hc;
        float cn = fs * cst[ci] + is * gt;
        cst[ci] = cn;
        float hn = os * tanhf(cn);
        hout[ci] = __float2half(hn);
        if (layer == 3)
            out[(size_t)bg_ * (TT * HH) + (size_t)t * HH + nh0 + hc] = hn;
    }
}

__global__ void copy_c4(float* __restrict__ out) {
    int i = blockIdx.x * blockDim.x + threadIdx.x;
    if (i < BB * HH) out[i] = g_c[3][i];
}

extern "C" void kernel_launch(void* const* d_in, const int* in_sizes, int n_in,
                              void* d_out, int out_size) {
    const float* x = (const float*)d_in[0];
    const float* W[4][4];  // [layer][Wih, Whh, bih, bhh]
    for (int l = 0; l < 4; l++)
        for (int j = 0; j < 4; j++)
            W[l][j] = (const float*)d_in[1 + l * 4 + j];
    float* out = (float*)d_out;

    conv_all<<<1184, 256>>>(x, W[0][0], W[0][1], W[1][0], W[1][1],
                               W[2][0], W[2][1], W[3][0], W[3][1]);
    init_state<<<(BB * HH + 255) / 256, 256>>>(
        W[0][2], W[0][3], W[1][2], W[1][3],
        W[2][2], W[2][3], W[3][2], W[3][3]);

    dim3 grid(HH / 32, BB / 64);  // 32 x 4 = 128 CTAs
    for (int t = 0; t < TT; t++) {
        int buf = t & 1;
        for (int l = 0; l < 4; l++)
            lstm_cell<<<grid, 256, SMEM_BYTES>>>(t, l, buf, out);
    }

    copy_c4<<<(BB * HH + 255) / 256, 256>>>(out + (size_t)BB * TT * HH);
}

// round 6
// speedup vs baseline: 7.2277x; 1.2205x over previous
#include <cuda_runtime.h>
#include <cuda_fp16.h>
#include <math.h>
#include <stdint.h>

#define BB 256
#define TT 100
#define NINN 64
#define HH 1024

// ---------------- persistent device state ----------------
__device__ __half g_x16[BB * TT * NINN];          // fp16 copy of x
__device__ __half g_wih0[4 * HH * NINN];          // layer 0 Wih
__device__ __half g_wih[3][4 * HH * HH];          // layers 1-3 Wih
__device__ __half g_whh[4][4 * HH * HH];          // Whh
__device__ __half g_h16[2][4][BB * HH];           // h state, double buffered (t parity)
__device__ float  g_c[4][BB * HH];                // c state (fp32)
__device__ float  g_bias[4][4 * HH];              // bih + bhh per layer

// ---------------- conversion / init ----------------
__global__ void conv_all(const float* __restrict__ x,
    const float* __restrict__ wi1, const float* __restrict__ wh1,
    const float* __restrict__ wi2, const float* __restrict__ wh2,
    const float* __restrict__ wi3, const float* __restrict__ wh3,
    const float* __restrict__ wi4, const float* __restrict__ wh4)
{
    const long NX  = BB * TT * NINN;
    const long NW0 = 4 * HH * NINN;
    const long NW  = 4L * HH * HH;
    const long total = NX + NW0 + 7L * NW;
    for (long i = blockIdx.x * (long)blockDim.x + threadIdx.x; i < total;
         i += (long)gridDim.x * blockDim.x) {
        long j = i;
        if (j < NX)  { g_x16[j]    = __float2half(x[j]);   continue; } j -= NX;
        if (j < NW0) { g_wih0[j]   = __float2half(wi1[j]); continue; } j -= NW0;
        if (j < NW)  { g_whh[0][j] = __float2half(wh1[j]); continue; } j -= NW;
        if (j < NW)  { g_wih[0][j] = __float2half(wi2[j]); continue; } j -= NW;
        if (j < NW)  { g_whh[1][j] = __float2half(wh2[j]); continue; } j -= NW;
        if (j < NW)  { g_wih[1][j] = __float2half(wi3[j]); continue; } j -= NW;
        if (j < NW)  { g_whh[2][j] = __float2half(wh3[j]); continue; } j -= NW;
        if (j < NW)  { g_wih[2][j] = __float2half(wi4[j]); continue; } j -= NW;
        g_whh[3][j] = __float2half(wh4[j]);
    }
}

__global__ void init_state(
    const float* __restrict__ bi1, const float* __restrict__ bh1,
    const float* __restrict__ bi2, const float* __restrict__ bh2,
    const float* __restrict__ bi3, const float* __restrict__ bh3,
    const float* __restrict__ bi4, const float* __restrict__ bh4)
{
    int i = blockIdx.x * blockDim.x + threadIdx.x;
    if (i < BB * HH) {
        __half z = __float2half(0.f);
        #pragma unroll
        for (int l = 0; l < 4; l++) {
            g_h16[0][l][i] = z;
            g_h16[1][l][i] = z;
            g_c[l][i] = 0.f;
        }
    }
    if (i < 4 * HH) {
        g_bias[0][i] = bi1[i] + bh1[i];
        g_bias[1][i] = bi2[i] + bh2[i];
        g_bias[2][i] = bi3[i] + bh3[i];
        g_bias[3][i] = bi4[i] + bh4[i];
    }
}

// ---------------- helpers ----------------
__device__ __forceinline__ uint32_t swz(uint32_t x) { return x ^ ((x >> 3) & 0x70); }

__device__ __forceinline__ void cpa16(uint32_t s, const void* g) {
    asm volatile("cp.async.cg.shared.global [%0], [%1], 16;" :: "r"(s), "l"(g));
}
__device__ __forceinline__ void ldm4(uint32_t* r, uint32_t a) {
    asm volatile("ldmatrix.sync.aligned.m8n8.x4.shared.b16 {%0,%1,%2,%3}, [%4];"
        : "=r"(r[0]), "=r"(r[1]), "=r"(r[2]), "=r"(r[3]) : "r"(a));
}
__device__ __forceinline__ void mma16816(float* d, const uint32_t* a, const uint32_t* b) {
    asm volatile(
        "mma.sync.aligned.m16n8k16.row.col.f32.f16.f16.f32 "
        "{%0,%1,%2,%3}, {%4,%5,%6,%7}, {%8,%9}, {%0,%1,%2,%3};"
        : "+f"(d[0]), "+f"(d[1]), "+f"(d[2]), "+f"(d[3])
        : "r"(a[0]), "r"(a[1]), "r"(a[2]), "r"(a[3]), "r"(b[0]), "r"(b[1]));
}

// 3-stage smem: per stage A 64x128B (8KB) + B 64x128B (8KB) = 16KB; 3 stages = 48KB.
// Epilogue stage S[64][66] floats (16.9KB) reuses the same storage after sync.
#define A_OFF(s) ((s) * 16384)
#define B_OFF(s) ((s) * 16384 + 8192)
#define SMEM_BYTES 49152

// Load one K-tile (A: 64x64 fp16, B: 64 gate-rows x 64 fp16) into stage s. 128 thr.
__device__ __forceinline__ void load_tile(
    uint32_t sb, int tid, int s, int m0, int nh0,
    const __half* __restrict__ Ap, int ldA,
    const __half* __restrict__ Wp, int ldW, int k0)
{
    #pragma unroll
    for (int i = 0; i < 4; i++) {              // A: 512 x 16B chunks
        int u = tid + i * 128;
        int r = u >> 3, c = u & 7;
        cpa16(sb + A_OFF(s) + swz(r * 128 + c * 16),
              Ap + (size_t)(m0 + r) * ldA + k0 + c * 8);
    }
    #pragma unroll
    for (int i = 0; i < 4; i++) {              // B: 512 x 16B chunks
        int u = tid + i * 128;
        int rr = u >> 3, c = u & 7;
        int wrow = (rr >> 4) * HH + nh0 + (rr & 15);   // 4 gates x 16 cols
        cpa16(sb + B_OFF(s) + swz(rr * 128 + c * 16),
              Wp + (size_t)wrow * ldW + k0 + c * 8);
    }
    asm volatile("cp.async.commit_group;" ::: "memory");
}

// Load ldmatrix fragments for one ks (K=16 step) into register buffer p.
__device__ __forceinline__ void frag_ld(
    uint32_t sA, uint32_t sB, int ks, int lane, int mw, int nw,
    uint32_t af[2][4], uint32_t bf[4][2])
{
    #pragma unroll
    for (int mt = 0; mt < 2; mt++) {
        int r  = mw * 32 + mt * 16 + (lane & 15);
        int kc = ks * 32 + (lane >> 4) * 16;
        ldm4(af[mt], sA + swz(r * 128 + kc));
    }
    #pragma unroll
    for (int np = 0; np < 2; np++) {
        int rr = nw * 32 + np * 16 + (lane & 7) + ((lane >> 4) << 3);
        int kc = ks * 32 + (((lane >> 3) & 1) << 4);
        uint32_t r4[4];
        ldm4(r4, sB + swz(rr * 128 + kc));
        bf[np * 2 + 0][0] = r4[0]; bf[np * 2 + 0][1] = r4[1];
        bf[np * 2 + 1][0] = r4[2]; bf[np * 2 + 1][1] = r4[3];
    }
}

// One LSTM cell. CTA: 64 batch rows x (4 gates x 16 hidden cols). 128 threads,
// 4 warps in a 2x2 grid of 32x32 warp tiles. Grid 256 -> ~2 CTAs/SM.
__global__ __launch_bounds__(128) void lstm_cell(
    int t, int layer, int buf, float* __restrict__ out)
{
    extern __shared__ __align__(16) unsigned char SM[];
    const uint32_t sb = (uint32_t)__cvta_generic_to_shared(SM);

    const int tid  = threadIdx.x;
    const int lane = tid & 31;
    const int w    = tid >> 5;
    const int mw   = w >> 1;          // 0..1 : 32-row m strip
    const int nw   = w & 1;           // 0..1 : 32-gate-row strip
    const int nh0  = blockIdx.x * 16; // hidden-col tile
    const int m0   = blockIdx.y * 64; // batch-row tile

    const int din = (layer == 0) ? NINN : HH;
    const __half* A0   = (layer == 0) ? (g_x16 + t * NINN) : g_h16[buf][layer - 1];
    const int     ldA0 = (layer == 0) ? TT * NINN : HH;
    const __half* Wih  = (layer == 0) ? g_wih0 : g_wih[layer - 1];
    const __half* Whh  = g_whh[layer];
    const __half* hin  = g_h16[buf ^ 1][layer];
    __half*       hout = g_h16[buf][layer];
    float*        cst  = g_c[layer];

    const int nt0 = din / 64;          // K tiles in input phase
    const int ntt = nt0 + HH / 64;     // + recurrent phase

    float acc[2][4][4];
    #pragma unroll
    for (int mt = 0; mt < 2; mt++)
        #pragma unroll
        for (int nt = 0; nt < 4; nt++)
            #pragma unroll
            for (int i = 0; i < 4; i++) acc[mt][nt][i] = 0.f;

    // prologue: fill stages 0 and 1
    load_tile(sb, tid, 0, m0, nh0, A0, ldA0, Wih, din, 0);
    {
        int jn = 1;
        if (jn < nt0) load_tile(sb, tid, 1, m0, nh0, A0, ldA0, Wih, din, jn * 64);
        else          load_tile(sb, tid, 1, m0, nh0, hin, HH, Whh, HH, (jn - nt0) * 64);
    }

    for (int j = 0; j < ntt; j++) {
        if (j < ntt - 1) { asm volatile("cp.async.wait_group 1;" ::: "memory"); }
        else             { asm volatile("cp.async.wait_group 0;" ::: "memory"); }
        __syncthreads();   // tile j visible to all; all warps done reading stage (j+2)%3

        if (j + 2 < ntt) {
            int jn = j + 2, s = jn % 3;
            if (jn < nt0) load_tile(sb, tid, s, m0, nh0, A0, ldA0, Wih, din, jn * 64);
            else          load_tile(sb, tid, s, m0, nh0, hin, HH, Whh, HH, (jn - nt0) * 64);
        }

        const uint32_t sA = sb + A_OFF(j % 3);
        const uint32_t sB = sb + B_OFF(j % 3);
        uint32_t af[2][2][4], bf[2][4][2];
        frag_ld(sA, sB, 0, lane, mw, nw, af[0], bf[0]);
        #pragma unroll
        for (int ks = 0; ks < 4; ks++) {
            int p = ks & 1;
            if (ks < 3) frag_ld(sA, sB, ks + 1, lane, mw, nw, af[p ^ 1], bf[p ^ 1]);
            #pragma unroll
            for (int mt = 0; mt < 2; mt++)
                #pragma unroll
                for (int nt = 0; nt < 4; nt++)
                    mma16816(acc[mt][nt], af[p][mt], bf[p][nt]);
        }
    }
    __syncthreads();

    // ---- stage accums to smem so each thread owns all 4 gates of (b, col) ----
    float* S = (float*)SM;  // [64][66]
    #pragma unroll
    for (int mt = 0; mt < 2; mt++)
        #pragma unroll
        for (int nt = 0; nt < 4; nt++) {
            int r = mw * 32 + mt * 16 + (lane >> 2);
            int c = nw * 32 + nt * 8 + 2 * (lane & 3);
            *(float2*)&S[r * 66 + c]       = make_float2(acc[mt][nt][0], acc[mt][nt][1]);
            *(float2*)&S[(r + 8) * 66 + c] = make_float2(acc[mt][nt][2], acc[mt][nt][3]);
        }
    __syncthreads();

    const int hc = tid & 15;  // hidden col (constant per thread)
    const float* bias = g_bias[layer];
    float bi  = bias[0 * HH + nh0 + hc];
    float bf_ = bias[1 * HH + nh0 + hc];
    float bg  = bias[2 * HH + nh0 + hc];
    float bo  = bias[3 * HH + nh0 + hc];

    #pragma unroll
    for (int i = 0; i < 8; i++) {
        int bl  = (tid >> 4) + i * 8;      // local batch row
        int bg_ = m0 + bl;                 // global batch row
        float vi = S[bl * 66 +  0 + hc] + bi;
        float vf = S[bl * 66 + 16 + hc] + bf_;
        float vg = S[bl * 66 + 32 + hc] + bg;
        float vo = S[bl * 66 + 48 + hc] + bo;
        float is = 1.f / (1.f + expf(-vi));
        float fs = 1.f / (1.f + expf(-vf));
        float gt = tanhf(vg);
        float os = 1.f / (1.f + expf(-vo));
        size_t ci = (size_t)bg_ * HH + nh0 + hc;
        float cn = fs * cst[ci] + is * gt;
        cst[ci] = cn;
        float hn = os * tanhf(cn);
        hout[ci] = __float2half(hn);
        if (layer == 3)
            out[(size_t)bg_ * (TT * HH) + (size_t)t * HH + nh0 + hc] = hn;
    }
}

__global__ void copy_c4(float* __restrict__ out) {
    int i = blockIdx.x * blockDim.x + threadIdx.x;
    if (i < BB * HH) out[i] = g_c[3][i];
}

extern "C" void kernel_launch(void* const* d_in, const int* in_sizes, int n_in,
                              void* d_out, int out_size) {
    const float* x = (const float*)d_in[0];
    const float* W[4][4];  // [layer][Wih, Whh, bih, bhh]
    for (int l = 0; l < 4; l++)
        for (int j = 0; j < 4; j++)
            W[l][j] = (const float*)d_in[1 + l * 4 + j];
    float* out = (float*)d_out;

    conv_all<<<1184, 256>>>(x, W[0][0], W[0][1], W[1][0], W[1][1],
                               W[2][0], W[2][1], W[3][0], W[3][1]);
    init_state<<<(BB * HH + 255) / 256, 256>>>(
        W[0][2], W[0][3], W[1][2], W[1][3],
        W[2][2], W[2][3], W[3][2], W[3][3]);

    dim3 grid(HH / 16, BB / 64);  // 64 x 4 = 256 CTAs
    for (int t = 0; t < TT; t++) {
        int buf = t & 1;
        for (int l = 0; l < 4; l++)
            lstm_cell<<<grid, 128, SMEM_BYTES>>>(t, l, buf, out);
    }

    copy_c4<<<(BB * HH + 255) / 256, 256>>>(out + (size_t)BB * TT * HH);
}